// round 12
// baseline (speedup 1.0000x reference)
#include <cuda_runtime.h>
#include <cuda_fp16.h>
#include <cstdint>

// Problem dims (fixed)
#define FDIM 1024
#define CDIM 128
#define BDIM 2048

#define BM 16
#define BN 128
#define BK 128
#define NITER (FDIM / BK)       // 8
#define NSTAGE 3
#define THREADS 512

// ---------------- scratch ----------------
__device__ __half g_b[CDIM * FDIM];   // softmax(w) fp16, [c][k] k-major

// ---------------- helpers ----------------
__device__ __forceinline__ uint32_t smem_u32(const void* p) {
    uint32_t a;
    asm("{ .reg .u64 t; cvta.to.shared.u64 t, %1; cvt.u32.u64 %0, t; }" : "=r"(a) : "l"(p));
    return a;
}
// 256B-row tile, 16B-granularity XOR swizzle
__device__ __forceinline__ uint32_t swz256(uint32_t row, uint32_t colByte) {
    return row * 256u + (colByte ^ ((row & 7u) << 4));
}
#define CP_ASYNC16(sm, g) asm volatile("cp.async.cg.shared.global [%0], [%1], 16;" :: "r"(sm), "l"(g) : "memory")
#define CP_COMMIT()       asm volatile("cp.async.commit_group;" ::: "memory")
#define CP_WAIT1()        asm volatile("cp.async.wait_group 1;" ::: "memory")
#define CP_WAIT0()        asm volatile("cp.async.wait_group 0;" ::: "memory")

#define LDMATRIX_X4(r0, r1, r2, r3, addr)                                        \
    asm volatile("ldmatrix.sync.aligned.m8n8.x4.shared.b16 {%0,%1,%2,%3}, [%4];" \
                 : "=r"(r0), "=r"(r1), "=r"(r2), "=r"(r3) : "r"(addr))
#define LDMATRIX_X2(r0, r1, addr)                                                \
    asm volatile("ldmatrix.sync.aligned.m8n8.x2.shared.b16 {%0,%1}, [%2];"       \
                 : "=r"(r0), "=r"(r1) : "r"(addr))

#define MMA_F16(d, a, b)                                                         \
    asm volatile("mma.sync.aligned.m16n8k16.row.col.f32.f16.f16.f32 "            \
                 "{%0,%1,%2,%3}, {%4,%5,%6,%7}, {%8,%9}, {%0,%1,%2,%3};"         \
                 : "+f"((d)[0]), "+f"((d)[1]), "+f"((d)[2]), "+f"((d)[3])        \
                 : "r"((a)[0]), "r"((a)[1]), "r"((a)[2]), "r"((a)[3]),           \
                   "r"((b)[0]), "r"((b)[1]))

// ---------------------------------------------------------------------------
// Kernel 1: one class per single-warp block (128 blocks). Triggers PDL at
// entry so the mma kernel's x-prologue overlaps this kernel entirely.
// ---------------------------------------------------------------------------
__global__ void __launch_bounds__(32) prep_w_kernel(const float* __restrict__ w) {
    cudaTriggerProgrammaticLaunchCompletion();
    const int c    = blockIdx.x;           // class 0..127
    const int lane = threadIdx.x;
    const float* row = w + (size_t)c * FDIM;

    float4 v[8];
    float m = -1e30f;
#pragma unroll
    for (int j = 0; j < 8; j++) {
        v[j] = *reinterpret_cast<const float4*>(row + j * 128 + lane * 4);
        m = fmaxf(m, fmaxf(fmaxf(v[j].x, v[j].y), fmaxf(v[j].z, v[j].w)));
    }
#pragma unroll
    for (int s = 16; s > 0; s >>= 1) m = fmaxf(m, __shfl_xor_sync(0xffffffffu, m, s));

    float sum = 0.0f;
#pragma unroll
    for (int j = 0; j < 8; j++) {
        v[j].x = __expf(v[j].x - m); v[j].y = __expf(v[j].y - m);
        v[j].z = __expf(v[j].z - m); v[j].w = __expf(v[j].w - m);
        sum += (v[j].x + v[j].y) + (v[j].z + v[j].w);
    }
#pragma unroll
    for (int s = 16; s > 0; s >>= 1) sum += __shfl_xor_sync(0xffffffffu, sum, s);
    const float inv = 1.0f / sum;

#pragma unroll
    for (int j = 0; j < 8; j++) {
        __half2 h01 = __floats2half2_rn(v[j].x * inv, v[j].y * inv);
        __half2 h23 = __floats2half2_rn(v[j].z * inv, v[j].w * inv);
        uint2 pv = make_uint2(*reinterpret_cast<uint32_t*>(&h01),
                              *reinterpret_cast<uint32_t*>(&h23));
        *reinterpret_cast<uint2*>(g_b + (size_t)c * FDIM + j * 128 + lane * 4) = pv;
    }
}

// ---------------------------------------------------------------------------
// Kernel 2: fused exp->fp16 HMMA GEMM->log. 128 CTAs x 512 threads (16 warps),
// warp tile 16x8. BK=128, 3-stage pipeline, register double-buffered
// fragments (LDSM k+1 issued before MMA k). PDL: x prologue runs before
// cudaGridDependencySynchronize(); B loads after.
// ---------------------------------------------------------------------------
#define OFF_A 0
#define OFF_B 4096
#define STAGE_BYTES 36864          // A 16x256B (4KB) + B 128x256B (32KB)
#define SMEM_TOTAL (NSTAGE * STAGE_BYTES)   // 110592

__device__ __forceinline__ void load_x(float4& xv, const float* __restrict__ xbase,
                                       int kOff, int tid) {
    const uint32_t row = (uint32_t)tid >> 5;    // 0..15
    const uint32_t c4  = (uint32_t)tid & 31;    // float4 within 128-col row
    xv = *reinterpret_cast<const float4*>(xbase + (size_t)row * FDIM + kOff + c4 * 4);
}

__device__ __forceinline__ void convert_x(char* stage, const float4 xv, int tid) {
    const uint32_t row = (uint32_t)tid >> 5;
    const uint32_t c4  = (uint32_t)tid & 31;
    __half2 h01 = __floats2half2_rn(__expf(xv.x), __expf(xv.y));
    __half2 h23 = __floats2half2_rn(__expf(xv.z), __expf(xv.w));
    uint2 pv = make_uint2(*reinterpret_cast<uint32_t*>(&h01),
                          *reinterpret_cast<uint32_t*>(&h23));
    const uint32_t byteOff = swz256(row, (c4 >> 1) * 16) + (c4 & 1) * 8;
    *reinterpret_cast<uint2*>(stage + OFF_A + byteOff) = pv;
}

__device__ __forceinline__ void issue_b(uint32_t stageBase, int kOff, int tid) {
#pragma unroll
    for (int t = 0; t < 4; t++) {
        const int idx = tid + t * THREADS;          // 0..2047
        const uint32_t row = (uint32_t)idx >> 4;    // 0..127
        const uint32_t c16 = (uint32_t)idx & 15;    // 16B chunk (8 fp16)
        const __half* src = g_b + (size_t)row * FDIM + kOff + c16 * 8;
        CP_ASYNC16(stageBase + OFF_B + swz256(row, c16 * 16), src);
    }
    CP_COMMIT();
}

__global__ void __launch_bounds__(THREADS) mma_kernel(const float* __restrict__ x,
                                                      float* __restrict__ out) {
    extern __shared__ char smem[];
    const uint32_t sbase = smem_u32(smem);
    const int tid  = threadIdx.x;
    const int warp = tid >> 5;     // 0..15 -> n8 tile
    const int lane = tid & 31;

    const int mtile = (int)blockIdx.x;   // 0..127

    float acc0[4], acc1[4];        // k-parity accumulator chains
#pragma unroll
    for (int e = 0; e < 4; e++) { acc0[e] = 0.0f; acc1[e] = 0.0f; }

    // ldmatrix lane address components
    const uint32_t aRow = (lane & 7) + ((lane >> 3) & 1) * 8;   // 0..15
    const uint32_t aCol = (lane >> 4) * 16;
    const uint32_t bRow = warp * 8 + (lane & 7);
    const uint32_t bCol = ((lane >> 3) & 1) * 16;               // lanes 0..15 used

    const float* xbase = x + (size_t)mtile * BM * FDIM;

    // ---- PDL-overlapped prologue: x loads + exp + STS (no g_b access) ----
    float4 xv0, xv1, xv;
    load_x(xv0, xbase, 0, tid);
    load_x(xv1, xbase, BK, tid);
    load_x(xv,  xbase, 2 * BK, tid);
    convert_x(smem + 0 * STAGE_BYTES, xv0, tid);
    convert_x(smem + 1 * STAGE_BYTES, xv1, tid);

    // ---- wait for prep_w's g_b, then start B pipeline ----
    cudaGridDependencySynchronize();
    issue_b(sbase + 0 * STAGE_BYTES, 0, tid);
    issue_b(sbase + 1 * STAGE_BYTES, BK, tid);
    CP_WAIT1();
    __syncthreads();

    float4 xnv;
#pragma unroll
    for (int it = 0; it < NITER; it++) {
        const uint32_t cur = sbase + (uint32_t)(it % 3) * STAGE_BYTES;
        const bool issue = (it + 2 < NITER);

        if (issue) {
            if (it + 3 < NITER) load_x(xnv, xbase, (it + 3) * BK, tid);
            const int s2 = (it + 2) % 3;
            convert_x(smem + s2 * STAGE_BYTES, xv, tid);
            issue_b(sbase + (uint32_t)s2 * STAGE_BYTES, (it + 2) * BK, tid);
        }

        // register double-buffered fragment pipeline over 8 ksteps
        uint32_t a[2][4], b[2][2];
        LDMATRIX_X4(a[0][0], a[0][1], a[0][2], a[0][3], cur + OFF_A + swz256(aRow, aCol));
        LDMATRIX_X2(b[0][0], b[0][1],                   cur + OFF_B + swz256(bRow, bCol));
#pragma unroll
        for (int ks = 0; ks < BK / 16; ks++) {
            const int cb = ks & 1;
            if (ks + 1 < BK / 16) {
                const uint32_t kb = (uint32_t)(ks + 1) * 32;
                LDMATRIX_X4(a[cb ^ 1][0], a[cb ^ 1][1], a[cb ^ 1][2], a[cb ^ 1][3],
                            cur + OFF_A + swz256(aRow, kb + aCol));
                LDMATRIX_X2(b[cb ^ 1][0], b[cb ^ 1][1],
                            cur + OFF_B + swz256(bRow, kb + bCol));
            }
            if (ks & 1) { MMA_F16(acc1, a[cb], b[cb]); } else { MMA_F16(acc0, a[cb], b[cb]); }
        }

        if (it + 1 < NITER) {
            if (issue) { CP_WAIT1(); } else { CP_WAIT0(); }
            __syncthreads();
        }
        if (it + 3 < NITER) xv = xnv;
    }

    // Epilogue: sum chains, log, direct store
    const float s0 = acc0[0] + acc1[0];
    const float s1 = acc0[1] + acc1[1];
    const float s2 = acc0[2] + acc1[2];
    const float s3 = acc0[3] + acc1[3];
    const int m = mtile * BM + (lane >> 2);
    const int n = warp * 8 + (lane & 3) * 2;
    *reinterpret_cast<float2*>(out + (size_t)m * CDIM + n) =
        make_float2(__logf(s0), __logf(s1));
    *reinterpret_cast<float2*>(out + (size_t)(m + 8) * CDIM + n) =
        make_float2(__logf(s2), __logf(s3));
}

// ---------------------------------------------------------------------------
extern "C" void kernel_launch(void* const* d_in, const int* in_sizes, int n_in,
                              void* d_out, int out_size) {
    const float* x = (const float*)d_in[0];
    const float* w = (const float*)d_in[1];
    if (n_in >= 2 && in_sizes[0] == CDIM * FDIM && in_sizes[1] == BDIM * FDIM) {
        w = (const float*)d_in[0];
        x = (const float*)d_in[1];
    }
    float* out = (float*)d_out;

    static bool attr_set = false;
    if (!attr_set) {
        cudaFuncSetAttribute(mma_kernel, cudaFuncAttributeMaxDynamicSharedMemorySize, SMEM_TOTAL);
        attr_set = true;
    }

    prep_w_kernel<<<CDIM, 32>>>(w);

    // mma with programmatic dependent launch: prologue overlaps prep_w
    cudaLaunchConfig_t cfg = {};
    cfg.gridDim = dim3(BDIM / BM);
    cfg.blockDim = dim3(THREADS);
    cfg.dynamicSmemBytes = SMEM_TOTAL;
    cfg.stream = 0;
    cudaLaunchAttribute at[1];
    at[0].id = cudaLaunchAttributeProgrammaticStreamSerialization;
    at[0].val.programmaticStreamSerializationAllowed = 1;
    cfg.attrs = at;
    cfg.numAttrs = 1;
    cudaLaunchKernelEx(&cfg, mma_kernel, x, out);
}

// round 13
// speedup vs baseline: 1.2696x; 1.2696x over previous
#include <cuda_runtime.h>
#include <cuda_fp16.h>
#include <cstdint>

// Problem dims (fixed)
#define FDIM 1024
#define CDIM 128
#define BDIM 2048

#define BM 16
#define BN 128
#define BK 128
#define NITER (FDIM / BK)       // 8
#define NSTAGE 3
#define THREADS 512

// ---------------- scratch ----------------
// Blocked, pre-swizzled: byte offset = kc*32768 + c*256 + ((kk*2) ^ ((c&7)<<4))
// for element (class c, k = kc*128 + kk). Each 32KB kc-block is contiguous ->
// one cp.async.bulk per stage.
__device__ __align__(16) __half g_b[CDIM * FDIM];

// ---------------- helpers ----------------
__device__ __forceinline__ uint32_t smem_u32(const void* p) {
    uint32_t a;
    asm("{ .reg .u64 t; cvta.to.shared.u64 t, %1; cvt.u32.u64 %0, t; }" : "=r"(a) : "l"(p));
    return a;
}
// 256B-row tile, 16B-granularity XOR swizzle (matches the gmem-baked layout)
__device__ __forceinline__ uint32_t swz256(uint32_t row, uint32_t colByte) {
    return row * 256u + (colByte ^ ((row & 7u) << 4));
}

#define MBAR_INIT(mb, n)  asm volatile("mbarrier.init.shared.b64 [%0], %1;" :: "r"((uint32_t)(mb)), "r"((uint32_t)(n)) : "memory")
#define MBAR_EXPECT_TX(mb, bytes) \
    asm volatile("mbarrier.arrive.expect_tx.shared.b64 _, [%0], %1;" :: "r"((uint32_t)(mb)), "r"((uint32_t)(bytes)) : "memory")
#define BULK_G2S(dst, src, bytes, mb) \
    asm volatile("cp.async.bulk.shared::cta.global.mbarrier::complete_tx::bytes [%0], [%1], %2, [%3];" \
                 :: "r"((uint32_t)(dst)), "l"(src), "r"((uint32_t)(bytes)), "r"((uint32_t)(mb)) : "memory")
#define MBAR_WAIT(mb, ph) do {                                                   \
    uint32_t _m = (uint32_t)(mb), _p = (uint32_t)(ph), _d;                       \
    asm volatile("{\n\t.reg .pred p;\n\t"                                        \
        "mbarrier.try_wait.parity.acquire.cta.shared::cta.b64 p, [%1], %2;\n\t"  \
        "selp.b32 %0, 1, 0, p;\n\t}" : "=r"(_d) : "r"(_m), "r"(_p) : "memory");  \
    if (!_d) {                                                                   \
        asm volatile("{\n\t.reg .pred P1;\n\t"                                   \
            "W_%=:\n\t"                                                          \
            "mbarrier.try_wait.parity.acquire.cta.shared::cta.b64 P1, [%0], %1, 0x989680;\n\t" \
            "@P1 bra.uni D_%=;\n\t"                                              \
            "bra.uni W_%=;\n\t"                                                  \
            "D_%=:\n\t}" :: "r"(_m), "r"(_p) : "memory");                        \
    }                                                                            \
} while (0)

#define LDMATRIX_X4(r0, r1, r2, r3, addr)                                        \
    asm volatile("ldmatrix.sync.aligned.m8n8.x4.shared.b16 {%0,%1,%2,%3}, [%4];" \
                 : "=r"(r0), "=r"(r1), "=r"(r2), "=r"(r3) : "r"(addr))
#define LDMATRIX_X2(r0, r1, addr)                                                \
    asm volatile("ldmatrix.sync.aligned.m8n8.x2.shared.b16 {%0,%1}, [%2];"       \
                 : "=r"(r0), "=r"(r1) : "r"(addr))

#define MMA_F16(d, a, b)                                                         \
    asm volatile("mma.sync.aligned.m16n8k16.row.col.f32.f16.f16.f32 "            \
                 "{%0,%1,%2,%3}, {%4,%5,%6,%7}, {%8,%9}, {%0,%1,%2,%3};"         \
                 : "+f"((d)[0]), "+f"((d)[1]), "+f"((d)[2]), "+f"((d)[3])        \
                 : "r"((a)[0]), "r"((a)[1]), "r"((a)[2]), "r"((a)[3]),           \
                   "r"((b)[0]), "r"((b)[1]))

// ---------------------------------------------------------------------------
// Kernel 1: warp-per-class softmax(weight) -> blocked+pre-swizzled g_b.
// ---------------------------------------------------------------------------
__global__ void __launch_bounds__(256) prep_w_kernel(const float* __restrict__ w) {
    const int c    = (blockIdx.x * 256 + threadIdx.x) >> 5;   // class 0..127
    const int lane = threadIdx.x & 31;
    const float* row = w + (size_t)c * FDIM;

    float4 v[8];
    float m = -1e30f;
#pragma unroll
    for (int j = 0; j < 8; j++) {
        v[j] = *reinterpret_cast<const float4*>(row + j * 128 + lane * 4);
        m = fmaxf(m, fmaxf(fmaxf(v[j].x, v[j].y), fmaxf(v[j].z, v[j].w)));
    }
#pragma unroll
    for (int s = 16; s > 0; s >>= 1) m = fmaxf(m, __shfl_xor_sync(0xffffffffu, m, s));

    float sum = 0.0f;
#pragma unroll
    for (int j = 0; j < 8; j++) {
        v[j].x = __expf(v[j].x - m); v[j].y = __expf(v[j].y - m);
        v[j].z = __expf(v[j].z - m); v[j].w = __expf(v[j].w - m);
        sum += (v[j].x + v[j].y) + (v[j].z + v[j].w);
    }
#pragma unroll
    for (int s = 16; s > 0; s >>= 1) sum += __shfl_xor_sync(0xffffffffu, sum, s);
    const float inv = 1.0f / sum;

    char* gbase = reinterpret_cast<char*>(g_b);
#pragma unroll
    for (int j = 0; j < 8; j++) {     // j = kc block, kk = lane*4
        __half2 h01 = __floats2half2_rn(v[j].x * inv, v[j].y * inv);
        __half2 h23 = __floats2half2_rn(v[j].z * inv, v[j].w * inv);
        uint2 pv = make_uint2(*reinterpret_cast<uint32_t*>(&h01),
                              *reinterpret_cast<uint32_t*>(&h23));
        const uint32_t off = (uint32_t)j * 32768u + (uint32_t)c * 256u +
                             (((uint32_t)lane * 8u) ^ (((uint32_t)c & 7u) << 4));
        *reinterpret_cast<uint2*>(gbase + off) = pv;
    }
}

// ---------------------------------------------------------------------------
// Kernel 2: fused exp->fp16 HMMA GEMM->log. 128 CTAs x 512 threads (16 warps),
// warp tile 16x8, BK=128, 3 stages. B per stage = ONE cp.async.bulk (32KB)
// into LDSM-ready (pre-swizzled) smem, gated by mbarrier expect_tx.
// LDSM addresses precomputed (relA/relB) -> minimal mainloop ALU.
// ---------------------------------------------------------------------------
#define MBAR_BASE 0                 // 3 x 8B mbarriers
#define STAGES_OFF 1024
#define OFF_A 0
#define OFF_B 4096
#define STAGE_BYTES 36864           // A 16x256B (4KB) + B 128x256B (32KB)
#define SMEM_TOTAL (STAGES_OFF + NSTAGE * STAGE_BYTES)   // 111616

__device__ __forceinline__ void load_x(float4& xv, const float* __restrict__ xbase,
                                       int kOff, int tid) {
    const uint32_t row = (uint32_t)tid >> 5;    // 0..15
    const uint32_t c4  = (uint32_t)tid & 31;    // float4 within 128-col row
    xv = *reinterpret_cast<const float4*>(xbase + (size_t)row * FDIM + kOff + c4 * 4);
}

__device__ __forceinline__ void convert_x(char* stage, const float4 xv, int tid) {
    const uint32_t row = (uint32_t)tid >> 5;
    const uint32_t c4  = (uint32_t)tid & 31;
    __half2 h01 = __floats2half2_rn(__expf(xv.x), __expf(xv.y));
    __half2 h23 = __floats2half2_rn(__expf(xv.z), __expf(xv.w));
    uint2 pv = make_uint2(*reinterpret_cast<uint32_t*>(&h01),
                          *reinterpret_cast<uint32_t*>(&h23));
    const uint32_t byteOff = swz256(row, (c4 >> 1) * 16) + (c4 & 1) * 8;
    *reinterpret_cast<uint2*>(stage + OFF_A + byteOff) = pv;
}

__global__ void __launch_bounds__(THREADS) mma_kernel(const float* __restrict__ x,
                                                      float* __restrict__ out) {
    extern __shared__ char smem[];
    const uint32_t sbase = smem_u32(smem);
    const int tid  = threadIdx.x;
    const int warp = tid >> 5;     // 0..15 -> n8 tile
    const int lane = tid & 31;

    const int mtile = (int)blockIdx.x;   // 0..127
    const char* gb = reinterpret_cast<const char*>(g_b);

    // mbarrier init
    if (tid == 0) {
#pragma unroll
        for (int s = 0; s < NSTAGE; s++) MBAR_INIT(sbase + MBAR_BASE + s * 8, 1);
    }

    float acc0[4], acc1[4];
#pragma unroll
    for (int e = 0; e < 4; e++) { acc0[e] = 0.0f; acc1[e] = 0.0f; }

    // Precompute stage-relative LDSM addresses
    const uint32_t aRow = (lane & 7) + ((lane >> 3) & 1) * 8;   // 0..15
    const uint32_t aCol = (lane >> 4) * 16;
    const uint32_t bRow = warp * 8 + (lane & 7);
    const uint32_t bCol = ((lane >> 3) & 1) * 16;               // lanes 0..15 used
    uint32_t relA[8], relB[8];
#pragma unroll
    for (int ks = 0; ks < 8; ks++) {
        relA[ks] = OFF_A + swz256(aRow, (uint32_t)ks * 32 + aCol);
        relB[ks] = OFF_B + swz256(bRow, (uint32_t)ks * 32 + bCol);
    }

    const float* xbase = x + (size_t)mtile * BM * FDIM;

    __syncthreads();   // mbarriers visible

    // ---- prologue: x stages 0,1 converted; B bulk for stages 0,1 issued ----
    float4 xv0, xv1, xv, xnv;
    load_x(xv0, xbase, 0, tid);
    load_x(xv1, xbase, BK, tid);
    load_x(xv,  xbase, 2 * BK, tid);
    if (tid == 0) {
        MBAR_EXPECT_TX(sbase + MBAR_BASE + 0 * 8, 32768);
        BULK_G2S(sbase + STAGES_OFF + 0 * STAGE_BYTES + OFF_B, gb + 0 * 32768, 32768,
                 sbase + MBAR_BASE + 0 * 8);
        MBAR_EXPECT_TX(sbase + MBAR_BASE + 1 * 8, 32768);
        BULK_G2S(sbase + STAGES_OFF + 1 * STAGE_BYTES + OFF_B, gb + 1 * 32768, 32768,
                 sbase + MBAR_BASE + 1 * 8);
    }
    convert_x(smem + STAGES_OFF + 0 * STAGE_BYTES, xv0, tid);
    convert_x(smem + STAGES_OFF + 1 * STAGE_BYTES, xv1, tid);
    __syncthreads();   // A stages 0,1 visible

#pragma unroll
    for (int it = 0; it < NITER; it++) {
        const int s = it % 3;
        const uint32_t cur = sbase + STAGES_OFF + (uint32_t)s * STAGE_BYTES;
        const int parity = (it / 3) & 1;
        const bool issue = (it + 2 < NITER);

        if (issue) {
            if (it + 3 < NITER) load_x(xnv, xbase, (it + 3) * BK, tid);
            const int s2 = (it + 2) % 3;
            convert_x(smem + STAGES_OFF + s2 * STAGE_BYTES, xv, tid);
            if (tid == 0) {
                MBAR_EXPECT_TX(sbase + MBAR_BASE + s2 * 8, 32768);
                BULK_G2S(sbase + STAGES_OFF + (uint32_t)s2 * STAGE_BYTES + OFF_B,
                         gb + (size_t)(it + 2) * 32768, 32768,
                         sbase + MBAR_BASE + s2 * 8);
            }
        }

        // wait for this stage's B tile
        MBAR_WAIT(sbase + MBAR_BASE + s * 8, parity);

#pragma unroll
        for (int ks = 0; ks < 8; ks++) {
            uint32_t a[4], b[2];
            LDMATRIX_X4(a[0], a[1], a[2], a[3], cur + relA[ks]);
            LDMATRIX_X2(b[0], b[1],             cur + relB[ks]);
            if (ks & 1) { MMA_F16(acc1, a, b); } else { MMA_F16(acc0, a, b); }
        }

        if (it + 1 < NITER) __syncthreads();
        if (it + 3 < NITER) xv = xnv;
    }

    // Epilogue: sum chains, log, direct store
    const float s0 = acc0[0] + acc1[0];
    const float s1 = acc0[1] + acc1[1];
    const float s2 = acc0[2] + acc1[2];
    const float s3 = acc0[3] + acc1[3];
    const int m = mtile * BM + (lane >> 2);
    const int n = warp * 8 + (lane & 3) * 2;
    *reinterpret_cast<float2*>(out + (size_t)m * CDIM + n) =
        make_float2(__logf(s0), __logf(s1));
    *reinterpret_cast<float2*>(out + (size_t)(m + 8) * CDIM + n) =
        make_float2(__logf(s2), __logf(s3));
}

// ---------------------------------------------------------------------------
extern "C" void kernel_launch(void* const* d_in, const int* in_sizes, int n_in,
                              void* d_out, int out_size) {
    const float* x = (const float*)d_in[0];
    const float* w = (const float*)d_in[1];
    if (n_in >= 2 && in_sizes[0] == CDIM * FDIM && in_sizes[1] == BDIM * FDIM) {
        w = (const float*)d_in[0];
        x = (const float*)d_in[1];
    }
    float* out = (float*)d_out;

    static bool attr_set = false;
    if (!attr_set) {
        cudaFuncSetAttribute(mma_kernel, cudaFuncAttributeMaxDynamicSharedMemorySize, SMEM_TOTAL);
        attr_set = true;
    }

    prep_w_kernel<<<CDIM / 8, 256>>>(w);
    mma_kernel<<<BDIM / BM, THREADS, SMEM_TOTAL>>>(x, out);
}

// round 14
// speedup vs baseline: 1.3455x; 1.0597x over previous
#include <cuda_runtime.h>
#include <cuda_fp16.h>
#include <cstdint>

// Problem dims (fixed)
#define FDIM 1024
#define CDIM 128
#define BDIM 2048

#define BM 16
#define BN 128
#define BK 128
#define NITER (FDIM / BK)       // 8
#define NSTAGE 3
#define THREADS 512

// ---------------- scratch ----------------
// Blocked, pre-swizzled: byte offset = kc*32768 + c*256 + ((kk*2) ^ ((c&7)<<4))
// for element (class c, k = kc*128 + kk). One cp.async.bulk per 32KB block.
__device__ __align__(16) __half g_b[CDIM * FDIM];

// ---------------- helpers ----------------
__device__ __forceinline__ uint32_t smem_u32(const void* p) {
    uint32_t a;
    asm("{ .reg .u64 t; cvta.to.shared.u64 t, %1; cvt.u32.u64 %0, t; }" : "=r"(a) : "l"(p));
    return a;
}
__device__ __forceinline__ uint32_t swz256(uint32_t row, uint32_t colByte) {
    return row * 256u + (colByte ^ ((row & 7u) << 4));
}

#define MBAR_INIT(mb, n)  asm volatile("mbarrier.init.shared.b64 [%0], %1;" :: "r"((uint32_t)(mb)), "r"((uint32_t)(n)) : "memory")
#define MBAR_EXPECT_TX(mb, bytes) \
    asm volatile("mbarrier.arrive.expect_tx.shared.b64 _, [%0], %1;" :: "r"((uint32_t)(mb)), "r"((uint32_t)(bytes)) : "memory")
#define BULK_G2S(dst, src, bytes, mb) \
    asm volatile("cp.async.bulk.shared::cta.global.mbarrier::complete_tx::bytes [%0], [%1], %2, [%3];" \
                 :: "r"((uint32_t)(dst)), "l"(src), "r"((uint32_t)(bytes)), "r"((uint32_t)(mb)) : "memory")
#define MBAR_WAIT(mb, ph) do {                                                   \
    uint32_t _m = (uint32_t)(mb), _p = (uint32_t)(ph), _d;                       \
    asm volatile("{\n\t.reg .pred p;\n\t"                                        \
        "mbarrier.try_wait.parity.acquire.cta.shared::cta.b64 p, [%1], %2;\n\t"  \
        "selp.b32 %0, 1, 0, p;\n\t}" : "=r"(_d) : "r"(_m), "r"(_p) : "memory");  \
    if (!_d) {                                                                   \
        asm volatile("{\n\t.reg .pred P1;\n\t"                                   \
            "W_%=:\n\t"                                                          \
            "mbarrier.try_wait.parity.acquire.cta.shared::cta.b64 P1, [%0], %1, 0x989680;\n\t" \
            "@P1 bra.uni D_%=;\n\t"                                              \
            "bra.uni W_%=;\n\t"                                                  \
            "D_%=:\n\t}" :: "r"(_m), "r"(_p) : "memory");                        \
    }                                                                            \
} while (0)

#define LDMATRIX_X4(r0, r1, r2, r3, addr)                                        \
    asm volatile("ldmatrix.sync.aligned.m8n8.x4.shared.b16 {%0,%1,%2,%3}, [%4];" \
                 : "=r"(r0), "=r"(r1), "=r"(r2), "=r"(r3) : "r"(addr))
#define LDMATRIX_X2(r0, r1, addr)                                                \
    asm volatile("ldmatrix.sync.aligned.m8n8.x2.shared.b16 {%0,%1}, [%2];"       \
                 : "=r"(r0), "=r"(r1) : "r"(addr))

#define MMA_F16(d, a, b)                                                         \
    asm volatile("mma.sync.aligned.m16n8k16.row.col.f32.f16.f16.f32 "            \
                 "{%0,%1,%2,%3}, {%4,%5,%6,%7}, {%8,%9}, {%0,%1,%2,%3};"         \
                 : "+f"((d)[0]), "+f"((d)[1]), "+f"((d)[2]), "+f"((d)[3])        \
                 : "r"((a)[0]), "r"((a)[1]), "r"((a)[2]), "r"((a)[3]),           \
                   "r"((b)[0]), "r"((b)[1]))

// ---------------------------------------------------------------------------
// Kernel 1: warp-per-class softmax(weight) -> blocked+pre-swizzled g_b.
// ---------------------------------------------------------------------------
__global__ void __launch_bounds__(256) prep_w_kernel(const float* __restrict__ w) {
    const int c    = (blockIdx.x * 256 + threadIdx.x) >> 5;   // class 0..127
    const int lane = threadIdx.x & 31;
    const float* row = w + (size_t)c * FDIM;

    float4 v[8];
    float m = -1e30f;
#pragma unroll
    for (int j = 0; j < 8; j++) {
        v[j] = *reinterpret_cast<const float4*>(row + j * 128 + lane * 4);
        m = fmaxf(m, fmaxf(fmaxf(v[j].x, v[j].y), fmaxf(v[j].z, v[j].w)));
    }
#pragma unroll
    for (int s = 16; s > 0; s >>= 1) m = fmaxf(m, __shfl_xor_sync(0xffffffffu, m, s));

    float sum = 0.0f;
#pragma unroll
    for (int j = 0; j < 8; j++) {
        v[j].x = __expf(v[j].x - m); v[j].y = __expf(v[j].y - m);
        v[j].z = __expf(v[j].z - m); v[j].w = __expf(v[j].w - m);
        sum += (v[j].x + v[j].y) + (v[j].z + v[j].w);
    }
#pragma unroll
    for (int s = 16; s > 0; s >>= 1) sum += __shfl_xor_sync(0xffffffffu, sum, s);
    const float inv = 1.0f / sum;

    char* gbase = reinterpret_cast<char*>(g_b);
#pragma unroll
    for (int j = 0; j < 8; j++) {     // j = kc block, kk = lane*4
        __half2 h01 = __floats2half2_rn(v[j].x * inv, v[j].y * inv);
        __half2 h23 = __floats2half2_rn(v[j].z * inv, v[j].w * inv);
        uint2 pv = make_uint2(*reinterpret_cast<uint32_t*>(&h01),
                              *reinterpret_cast<uint32_t*>(&h23));
        const uint32_t off = (uint32_t)j * 32768u + (uint32_t)c * 256u +
                             (((uint32_t)lane * 8u) ^ (((uint32_t)c & 7u) << 4));
        *reinterpret_cast<uint2*>(gbase + off) = pv;
    }
}

// ---------------------------------------------------------------------------
// Kernel 2: max-MLP x read + resident-A HMMA GEMM. 128 CTAs x 512 threads.
// Prologue: ALL 8 x-LDG.128 per thread issued back-to-back (64KB/CTA in
// flight -> DRAM saturated), exp+STS into a FULL 32KB A tile once.
// Mainloop: B-only staging (3 x 32KB bulk buffers, mbarrier) + LDSM/MMA.
// ---------------------------------------------------------------------------
#define MBAR_BASE 0                 // 3 x 8B mbarriers
#define A_OFF 1024                  // full A: 8 kc-blocks x 4KB = 32KB
#define B_OFF (A_OFF + 32768)       // 3 stage buffers x 32KB
#define SMEM_TOTAL (B_OFF + NSTAGE * 32768)   // 132096

__global__ void __launch_bounds__(THREADS) mma_kernel(const float* __restrict__ x,
                                                      float* __restrict__ out) {
    extern __shared__ char smem[];
    const uint32_t sbase = smem_u32(smem);
    const int tid  = threadIdx.x;
    const int warp = tid >> 5;     // 0..15 -> n8 tile
    const int lane = tid & 31;

    const int mtile = (int)blockIdx.x;   // 0..127
    const char* gb = reinterpret_cast<const char*>(g_b);

    // ---- FIRST: all x loads, maximal MLP ----
    const float* xbase = x + (size_t)mtile * BM * FDIM;
    const uint32_t xrow = (uint32_t)tid >> 5;    // 0..15
    const uint32_t xc4  = (uint32_t)tid & 31;    // float4 col within 128-float chunk
    float4 xv[8];
#pragma unroll
    for (int j = 0; j < 8; j++)
        xv[j] = *reinterpret_cast<const float4*>(
            xbase + (size_t)xrow * FDIM + j * 128 + xc4 * 4);

    // ---- mbarrier init + first B bulk stages ----
    if (tid == 0) {
#pragma unroll
        for (int s = 0; s < NSTAGE; s++) MBAR_INIT(sbase + MBAR_BASE + s * 8, 1);
        asm volatile("fence.proxy.async.shared::cta;" ::: "memory");
#pragma unroll
        for (int s = 0; s < NSTAGE; s++) {
            MBAR_EXPECT_TX(sbase + MBAR_BASE + s * 8, 32768);
            BULK_G2S(sbase + B_OFF + s * 32768, gb + (size_t)s * 32768, 32768,
                     sbase + MBAR_BASE + s * 8);
        }
    }

    // ---- convert all x -> full A tile (stalls on DRAM arrivals) ----
#pragma unroll
    for (int j = 0; j < 8; j++) {
        __half2 h01 = __floats2half2_rn(__expf(xv[j].x), __expf(xv[j].y));
        __half2 h23 = __floats2half2_rn(__expf(xv[j].z), __expf(xv[j].w));
        uint2 pv = make_uint2(*reinterpret_cast<uint32_t*>(&h01),
                              *reinterpret_cast<uint32_t*>(&h23));
        const uint32_t byteOff = (uint32_t)j * 4096u +
                                 swz256(xrow, (xc4 >> 1) * 16) + (xc4 & 1) * 8;
        *reinterpret_cast<uint2*>(smem + A_OFF + byteOff) = pv;
    }

    // accumulators + precomputed LDSM offsets
    float acc0[4], acc1[4];
#pragma unroll
    for (int e = 0; e < 4; e++) { acc0[e] = 0.0f; acc1[e] = 0.0f; }
    const uint32_t aRow = (lane & 7) + ((lane >> 3) & 1) * 8;
    const uint32_t aCol = (lane >> 4) * 16;
    const uint32_t bRow = warp * 8 + (lane & 7);
    const uint32_t bCol = ((lane >> 3) & 1) * 16;
    uint32_t relA[8], relB[8];
#pragma unroll
    for (int ks = 0; ks < 8; ks++) {
        relA[ks] = swz256(aRow, (uint32_t)ks * 32 + aCol);
        relB[ks] = swz256(bRow, (uint32_t)ks * 32 + bCol);
    }

    __syncthreads();   // A tile + mbar init visible

#pragma unroll
    for (int it = 0; it < NITER; it++) {
        const int s = it % 3;
        const uint32_t curA = sbase + A_OFF + (uint32_t)it * 4096u;
        const uint32_t curB = sbase + B_OFF + (uint32_t)s * 32768u;
        const int parity = (it / 3) & 1;

        MBAR_WAIT(sbase + MBAR_BASE + s * 8, parity);

#pragma unroll
        for (int ks = 0; ks < 8; ks++) {
            uint32_t a[4], b[2];
            LDMATRIX_X4(a[0], a[1], a[2], a[3], curA + relA[ks]);
            LDMATRIX_X2(b[0], b[1],             curB + relB[ks]);
            if (ks & 1) { MMA_F16(acc1, a, b); } else { MMA_F16(acc0, a, b); }
        }

        if (it + 3 < NITER) {
            __syncthreads();   // all warps done reading buffer s
            if (tid == 0) {
                MBAR_EXPECT_TX(sbase + MBAR_BASE + s * 8, 32768);
                BULK_G2S(curB, gb + (size_t)(it + 3) * 32768, 32768,
                         sbase + MBAR_BASE + s * 8);
            }
        }
    }

    // Epilogue: sum chains, log, direct store
    const float s0 = acc0[0] + acc1[0];
    const float s1 = acc0[1] + acc1[1];
    const float s2 = acc0[2] + acc1[2];
    const float s3 = acc0[3] + acc1[3];
    const int m = mtile * BM + (lane >> 2);
    const int n = warp * 8 + (lane & 3) * 2;
    *reinterpret_cast<float2*>(out + (size_t)m * CDIM + n) =
        make_float2(__logf(s0), __logf(s1));
    *reinterpret_cast<float2*>(out + (size_t)(m + 8) * CDIM + n) =
        make_float2(__logf(s2), __logf(s3));
}

// ---------------------------------------------------------------------------
extern "C" void kernel_launch(void* const* d_in, const int* in_sizes, int n_in,
                              void* d_out, int out_size) {
    const float* x = (const float*)d_in[0];
    const float* w = (const float*)d_in[1];
    if (n_in >= 2 && in_sizes[0] == CDIM * FDIM && in_sizes[1] == BDIM * FDIM) {
        w = (const float*)d_in[0];
        x = (const float*)d_in[1];
    }
    float* out = (float*)d_out;

    static bool attr_set = false;
    if (!attr_set) {
        cudaFuncSetAttribute(mma_kernel, cudaFuncAttributeMaxDynamicSharedMemorySize, SMEM_TOTAL);
        attr_set = true;
    }

    prep_w_kernel<<<CDIM / 8, 256>>>(w);
    mma_kernel<<<BDIM / BM, THREADS, SMEM_TOTAL>>>(x, out);
}

// round 15
// speedup vs baseline: 1.3560x; 1.0079x over previous
#include <cuda_runtime.h>
#include <cuda_fp16.h>
#include <cstdint>

// Problem dims (fixed)
#define FDIM 1024
#define CDIM 128
#define BDIM 2048

#define BM 16
#define BN 128
#define BK 128
#define NITER (FDIM / BK)       // 8 chunks total, 4 per k-half
#define THREADS 512

// ---------------- scratch ----------------
// Blocked, pre-swizzled: byte offset = kc*32768 + c*256 + ((kk*2) ^ ((c&7)<<4))
__device__ __align__(16) __half g_b[CDIM * FDIM];

// ---------------- helpers ----------------
__device__ __forceinline__ uint32_t smem_u32(const void* p) {
    uint32_t a;
    asm("{ .reg .u64 t; cvta.to.shared.u64 t, %1; cvt.u32.u64 %0, t; }" : "=r"(a) : "l"(p));
    return a;
}
__device__ __forceinline__ uint32_t swz256(uint32_t row, uint32_t colByte) {
    return row * 256u + (colByte ^ ((row & 7u) << 4));
}

#define MBAR_INIT(mb, n)  asm volatile("mbarrier.init.shared.b64 [%0], %1;" :: "r"((uint32_t)(mb)), "r"((uint32_t)(n)) : "memory")
#define MBAR_EXPECT_TX(mb, bytes) \
    asm volatile("mbarrier.arrive.expect_tx.shared.b64 _, [%0], %1;" :: "r"((uint32_t)(mb)), "r"((uint32_t)(bytes)) : "memory")
#define BULK_G2S(dst, src, bytes, mb) \
    asm volatile("cp.async.bulk.shared::cta.global.mbarrier::complete_tx::bytes [%0], [%1], %2, [%3];" \
                 :: "r"((uint32_t)(dst)), "l"(src), "r"((uint32_t)(bytes)), "r"((uint32_t)(mb)) : "memory")
#define MBAR_WAIT(mb, ph) do {                                                   \
    uint32_t _m = (uint32_t)(mb), _p = (uint32_t)(ph), _d;                       \
    asm volatile("{\n\t.reg .pred p;\n\t"                                        \
        "mbarrier.try_wait.parity.acquire.cta.shared::cta.b64 p, [%1], %2;\n\t"  \
        "selp.b32 %0, 1, 0, p;\n\t}" : "=r"(_d) : "r"(_m), "r"(_p) : "memory");  \
    if (!_d) {                                                                   \
        asm volatile("{\n\t.reg .pred P1;\n\t"                                   \
            "W_%=:\n\t"                                                          \
            "mbarrier.try_wait.parity.acquire.cta.shared::cta.b64 P1, [%0], %1, 0x989680;\n\t" \
            "@P1 bra.uni D_%=;\n\t"                                              \
            "bra.uni W_%=;\n\t"                                                  \
            "D_%=:\n\t}" :: "r"(_m), "r"(_p) : "memory");                        \
    }                                                                            \
} while (0)

#define LDMATRIX_X4(r0, r1, r2, r3, addr)                                        \
    asm volatile("ldmatrix.sync.aligned.m8n8.x4.shared.b16 {%0,%1,%2,%3}, [%4];" \
                 : "=r"(r0), "=r"(r1), "=r"(r2), "=r"(r3) : "r"(addr))

#define MMA_F16(d, a, b)                                                         \
    asm volatile("mma.sync.aligned.m16n8k16.row.col.f32.f16.f16.f32 "            \
                 "{%0,%1,%2,%3}, {%4,%5,%6,%7}, {%8,%9}, {%0,%1,%2,%3};"         \
                 : "+f"((d)[0]), "+f"((d)[1]), "+f"((d)[2]), "+f"((d)[3])        \
                 : "r"((a)[0]), "r"((a)[1]), "r"((a)[2]), "r"((a)[3]),           \
                   "r"((b)[0]), "r"((b)[1]))

// ---------------------------------------------------------------------------
// Kernel 1: warp-per-class softmax(weight) -> blocked+pre-swizzled g_b.
// ---------------------------------------------------------------------------
__global__ void __launch_bounds__(256) prep_w_kernel(const float* __restrict__ w) {
    const int c    = (blockIdx.x * 256 + threadIdx.x) >> 5;   // class 0..127
    const int lane = threadIdx.x & 31;
    const float* row = w + (size_t)c * FDIM;

    float4 v[8];
    float m = -1e30f;
#pragma unroll
    for (int j = 0; j < 8; j++) {
        v[j] = *reinterpret_cast<const float4*>(row + j * 128 + lane * 4);
        m = fmaxf(m, fmaxf(fmaxf(v[j].x, v[j].y), fmaxf(v[j].z, v[j].w)));
    }
#pragma unroll
    for (int s = 16; s > 0; s >>= 1) m = fmaxf(m, __shfl_xor_sync(0xffffffffu, m, s));

    float sum = 0.0f;
#pragma unroll
    for (int j = 0; j < 8; j++) {
        v[j].x = __expf(v[j].x - m); v[j].y = __expf(v[j].y - m);
        v[j].z = __expf(v[j].z - m); v[j].w = __expf(v[j].w - m);
        sum += (v[j].x + v[j].y) + (v[j].z + v[j].w);
    }
#pragma unroll
    for (int s = 16; s > 0; s >>= 1) sum += __shfl_xor_sync(0xffffffffu, sum, s);
    const float inv = 1.0f / sum;

    char* gbase = reinterpret_cast<char*>(g_b);
#pragma unroll
    for (int j = 0; j < 8; j++) {
        __half2 h01 = __floats2half2_rn(v[j].x * inv, v[j].y * inv);
        __half2 h23 = __floats2half2_rn(v[j].z * inv, v[j].w * inv);
        uint2 pv = make_uint2(*reinterpret_cast<uint32_t*>(&h01),
                              *reinterpret_cast<uint32_t*>(&h23));
        const uint32_t off = (uint32_t)j * 32768u + (uint32_t)c * 256u +
                             (((uint32_t)lane * 8u) ^ (((uint32_t)c & 7u) << 4));
        *reinterpret_cast<uint2*>(gbase + off) = pv;
    }
}

// ---------------------------------------------------------------------------
// Kernel 2: max-MLP x read + resident-A, K-half-split HMMA GEMM.
// 128 CTAs x 512 threads. Warps: kh = warp>>3 (K half), nw = warp&7
// (warp tile 16x16 over BN=128). kh0 handles chunks 0-3 (bufs 0-3, p0);
// kh1 handles 4 (buf4,p0), 5..7 (bufs 0..2, p1, recycled after kh0's
// iters via a kh0-only named barrier). kh1 STS partials; kh0 reduces+log.
// ---------------------------------------------------------------------------
#define MBAR_BASE 0                 // 5 x 8B mbarriers
#define A_OFF 1024                  // 32KB full A (8 chunks x 4KB)
#define B_OFF (A_OFF + 32768)       // 5 x 32KB B buffers
#define RED_OFF (B_OFF + 5 * 32768) // 8KB reduce buffer
#define SMEM_TOTAL (RED_OFF + 8192) // 205824

__global__ void __launch_bounds__(THREADS) mma_kernel(const float* __restrict__ x,
                                                      float* __restrict__ out) {
    extern __shared__ char smem[];
    const uint32_t sbase = smem_u32(smem);
    const int tid  = threadIdx.x;
    const int warp = tid >> 5;
    const int lane = tid & 31;
    const int kh   = warp >> 3;    // 0: chunks 0-3, 1: chunks 4-7
    const int nw   = warp & 7;     // cols [nw*16, +16)

    const int mtile = (int)blockIdx.x;   // 0..127
    const char* gb = reinterpret_cast<const char*>(g_b);

    // ---- FIRST: all x loads, maximal MLP ----
    const float* xbase = x + (size_t)mtile * BM * FDIM;
    const uint32_t xrow = (uint32_t)tid >> 5;    // 0..15
    const uint32_t xc4  = (uint32_t)tid & 31;
    float4 xv[8];
#pragma unroll
    for (int j = 0; j < 8; j++)
        xv[j] = *reinterpret_cast<const float4*>(
            xbase + (size_t)xrow * FDIM + j * 128 + xc4 * 4);

    // ---- mbar init + B bulk for chunks 0..4 ----
    if (tid == 0) {
#pragma unroll
        for (int s = 0; s < 5; s++) MBAR_INIT(sbase + MBAR_BASE + s * 8, 1);
        asm volatile("fence.proxy.async.shared::cta;" ::: "memory");
#pragma unroll
        for (int s = 0; s < 5; s++) {
            MBAR_EXPECT_TX(sbase + MBAR_BASE + s * 8, 32768);
            BULK_G2S(sbase + B_OFF + s * 32768, gb + (size_t)s * 32768, 32768,
                     sbase + MBAR_BASE + s * 8);
        }
    }

    // ---- convert all x -> full resident A tile ----
#pragma unroll
    for (int j = 0; j < 8; j++) {
        __half2 h01 = __floats2half2_rn(__expf(xv[j].x), __expf(xv[j].y));
        __half2 h23 = __floats2half2_rn(__expf(xv[j].z), __expf(xv[j].w));
        uint2 pv = make_uint2(*reinterpret_cast<uint32_t*>(&h01),
                              *reinterpret_cast<uint32_t*>(&h23));
        const uint32_t byteOff = (uint32_t)j * 4096u +
                                 swz256(xrow, (xc4 >> 1) * 16) + (xc4 & 1) * 8;
        *reinterpret_cast<uint2*>(smem + A_OFF + byteOff) = pv;
    }

    float acc[2][2][4];            // [parity][ni]
#pragma unroll
    for (int p = 0; p < 2; p++)
#pragma unroll
        for (int j = 0; j < 2; j++)
#pragma unroll
            for (int e = 0; e < 4; e++) acc[p][j][e] = 0.0f;

    const uint32_t aRow = (lane & 7) + ((lane >> 3) & 1) * 8;
    const uint32_t aCol = (lane >> 4) * 16;
    const uint32_t bRow = nw * 16 + ((lane >> 4) & 1) * 8 + (lane & 7);
    const uint32_t bCol = ((lane >> 3) & 1) * 16;
    uint32_t relA[8], relB[8];
#pragma unroll
    for (int ks = 0; ks < 8; ks++) {
        relA[ks] = swz256(aRow, (uint32_t)ks * 32 + aCol);
        relB[ks] = swz256(bRow, (uint32_t)ks * 32 + bCol);
    }

    __syncthreads();   // A tile + mbarriers visible

    // ---- mainloop: 4 iters per k-half ----
#pragma unroll
    for (int i = 0; i < 4; i++) {
        const int chunk = kh * 4 + i;
        // buffer + parity mapping
        int buf, parity;
        if (kh == 0) { buf = i; parity = 0; }
        else         { buf = (i == 0) ? 4 : (i - 1); parity = (i == 0) ? 0 : 1; }

        MBAR_WAIT(sbase + MBAR_BASE + buf * 8, parity);

        const uint32_t curA = sbase + A_OFF + (uint32_t)chunk * 4096u;
        const uint32_t curB = sbase + B_OFF + (uint32_t)buf * 32768u;
#pragma unroll
        for (int ks = 0; ks < 8; ks++) {
            uint32_t a[4], b[4];
            LDMATRIX_X4(a[0], a[1], a[2], a[3], curA + relA[ks]);
            LDMATRIX_X4(b[0], b[1], b[2], b[3], curB + relB[ks]);
            const int p = ks & 1;
            MMA_F16(acc[p][0], a, b);
            MMA_F16(acc[p][1], a, b + 2);
        }

        // kh0 recycles its finished buffer i for chunk 5+i (kh1's later iters)
        if (kh == 0 && i < 3) {
            asm volatile("bar.sync 1, 256;" ::: "memory");   // kh0 warps only
            if (tid == 0) {
                MBAR_EXPECT_TX(sbase + MBAR_BASE + i * 8, 32768);
                BULK_G2S(sbase + B_OFF + (uint32_t)i * 32768u,
                         gb + (size_t)(5 + i) * 32768, 32768,
                         sbase + MBAR_BASE + i * 8);
            }
        }
    }

    // ---- reduction: kh1 publishes, kh0 combines + log + store ----
    float s[2][4];
#pragma unroll
    for (int j = 0; j < 2; j++)
#pragma unroll
        for (int e = 0; e < 4; e++) s[j][e] = acc[0][j][e] + acc[1][j][e];

    float* red = reinterpret_cast<float*>(smem + RED_OFF);
    const uint32_t r0 = lane >> 2;              // 0..7
    const uint32_t cb = (lane & 3) * 2;
    if (kh == 1) {
        float* dst = red + (size_t)nw * 256;    // 16x16 tile
#pragma unroll
        for (int ni = 0; ni < 2; ni++) {
            const uint32_t c = ni * 8 + cb;
            *reinterpret_cast<float2*>(dst + r0 * 16 + c)       = make_float2(s[ni][0], s[ni][1]);
            *reinterpret_cast<float2*>(dst + (r0 + 8) * 16 + c) = make_float2(s[ni][2], s[ni][3]);
        }
    }
    __syncthreads();
    if (kh == 0) {
        const float* src = red + (size_t)nw * 256;
#pragma unroll
        for (int ni = 0; ni < 2; ni++) {
            const uint32_t c = ni * 8 + cb;
            float2 v0 = *reinterpret_cast<const float2*>(src + r0 * 16 + c);
            float2 v1 = *reinterpret_cast<const float2*>(src + (r0 + 8) * 16 + c);
            const float t0 = s[ni][0] + v0.x;
            const float t1 = s[ni][1] + v0.y;
            const float t2 = s[ni][2] + v1.x;
            const float t3 = s[ni][3] + v1.y;
            const int m = mtile * BM + (int)r0;
            const int n = nw * 16 + ni * 8 + (int)cb;
            *reinterpret_cast<float2*>(out + (size_t)m * CDIM + n) =
                make_float2(__logf(t0), __logf(t1));
            *reinterpret_cast<float2*>(out + (size_t)(m + 8) * CDIM + n) =
                make_float2(__logf(t2), __logf(t3));
        }
    }
}

// ---------------------------------------------------------------------------
extern "C" void kernel_launch(void* const* d_in, const int* in_sizes, int n_in,
                              void* d_out, int out_size) {
    const float* x = (const float*)d_in[0];
    const float* w = (const float*)d_in[1];
    if (n_in >= 2 && in_sizes[0] == CDIM * FDIM && in_sizes[1] == BDIM * FDIM) {
        w = (const float*)d_in[0];
        x = (const float*)d_in[1];
    }
    float* out = (float*)d_out;

    static bool attr_set = false;
    if (!attr_set) {
        cudaFuncSetAttribute(mma_kernel, cudaFuncAttributeMaxDynamicSharedMemorySize, SMEM_TOTAL);
        attr_set = true;
    }

    prep_w_kernel<<<CDIM / 8, 256>>>(w);
    mma_kernel<<<BDIM / BM, THREADS, SMEM_TOTAL>>>(x, out);
}